// round 12
// baseline (speedup 1.0000x reference)
#include <cuda_runtime.h>
#include <cuda_bf16.h>
#include <math.h>
#include <stdint.h>

#define D 768
#define MAXN 50000
#define MAXE 100000

typedef __nv_bfloat16 bf16;

// ---------------- scratch (__device__ globals; no allocations allowed) ------
__device__ float g_e[(size_t)512 * D];        // bond-type table (512 rows)
__device__ float g_u[(size_t)MAXN * D];       // layer MLP output (fp32)
__device__ int   g_deg[MAXN];                 // degree histogram
__device__ int   g_off[MAXN + 1];             // CSR offsets
__device__ int   g_cur[MAXN];                 // fill cursors
__device__ int   g_csr[MAXE];                 // packed (src | etype<<16) by dst
__device__ bf16  g_s0h[(size_t)MAXN * D];     // GEMM1 input, split hi
__device__ bf16  g_s0l[(size_t)MAXN * D];     //                    lo
__device__ bf16  g_s1h[(size_t)MAXN * D];     // GEMM2 input, split hi
__device__ bf16  g_s1l[(size_t)MAXN * D];     //                    lo
__device__ bf16  g_wthi[(size_t)12 * D * D];  // W^T split hi  [z][n][k]
__device__ bf16  g_wtlo[(size_t)12 * D * D];  // W^T split lo

__device__ __forceinline__ float gelu_f(float x) {
    float x3 = x * x * x;
    return 0.5f * x * (1.0f + tanhf(0.7978845608028654f * (x + 0.044715f * x3)));
}
__device__ __forceinline__ uint32_t smem_u32(const void* p) {
    uint32_t a;
    asm("{ .reg .u64 t; cvta.to.shared.u64 t, %1; cvt.u32.u64 %0, t; }" : "=r"(a) : "l"(p));
    return a;
}
__device__ __forceinline__ uint32_t sw64(uint32_t off) { return off ^ ((off >> 3) & 0x30); }

__device__ __forceinline__ void ldm_x4(uint32_t* r, uint32_t a) {
    asm volatile("ldmatrix.sync.aligned.m8n8.x4.shared.b16 {%0,%1,%2,%3}, [%4];"
        : "=r"(r[0]), "=r"(r[1]), "=r"(r[2]), "=r"(r[3]) : "r"(a));
}
__device__ __forceinline__ void mma_bf16(float* c, const uint32_t* a, const uint32_t* b) {
    asm volatile("mma.sync.aligned.m16n8k16.row.col.f32.bf16.bf16.f32 "
        "{%0,%1,%2,%3},{%4,%5,%6,%7},{%8,%9},{%0,%1,%2,%3};"
        : "+f"(c[0]), "+f"(c[1]), "+f"(c[2]), "+f"(c[3])
        : "r"(a[0]), "r"(a[1]), "r"(a[2]), "r"(a[3]), "r"(b[0]), "r"(b[1]));
}
// pack 4 fp32 -> (hi uint2, lo uint2) bf16 split
__device__ __forceinline__ void split4(float4 a, uint2& hp, uint2& lp) {
    bf16 h0 = __float2bfloat16_rn(a.x), h1 = __float2bfloat16_rn(a.y);
    bf16 h2 = __float2bfloat16_rn(a.z), h3 = __float2bfloat16_rn(a.w);
    bf16 l0 = __float2bfloat16_rn(a.x - __bfloat162float(h0));
    bf16 l1 = __float2bfloat16_rn(a.y - __bfloat162float(h1));
    bf16 l2 = __float2bfloat16_rn(a.z - __bfloat162float(h2));
    bf16 l3 = __float2bfloat16_rn(a.w - __bfloat162float(h3));
    __nv_bfloat162 a0 = __halves2bfloat162(h0, h1), a1 = __halves2bfloat162(h2, h3);
    __nv_bfloat162 b0 = __halves2bfloat162(l0, l1), b1 = __halves2bfloat162(l2, l3);
    hp = make_uint2(*(uint32_t*)&a0, *(uint32_t*)&a1);
    lp = make_uint2(*(uint32_t*)&b0, *(uint32_t*)&b1);
}

// ---------------------------------------------------------------------------
// W transpose + bf16 split:  Wt_hi/lo[z][n][k] = split(W_z[k][n])
// ---------------------------------------------------------------------------
__global__ void split_transpose_w(const float* __restrict__ aw1, const float* __restrict__ aw2,
                                  const float* __restrict__ bw1, const float* __restrict__ bw2,
                                  const float* __restrict__ cw1, const float* __restrict__ cw2,
                                  bf16* __restrict__ hi, bf16* __restrict__ lo)
{
    __shared__ float t[32][33];
    int z = blockIdx.z;
    const float* W;
    if      (z == 0) W = aw1;
    else if (z == 1) W = aw2;
    else if (z == 2) W = bw1;
    else if (z == 3) W = bw2;
    else if (z < 8)  W = cw1 + (size_t)(z - 4) * D * D;
    else             W = cw2 + (size_t)(z - 8) * D * D;

    int n0 = blockIdx.x * 32, k0 = blockIdx.y * 32;
    int tx = threadIdx.x, ty = threadIdx.y;     // (32, 8)
    #pragma unroll
    for (int i = 0; i < 4; i++)
        t[ty + i * 8][tx] = W[(size_t)(k0 + ty + i * 8) * D + n0 + tx];
    __syncthreads();
    #pragma unroll
    for (int i = 0; i < 4; i++) {
        float v = t[tx][ty + i * 8];
        bf16 h = __float2bfloat16_rn(v);
        bf16 l = __float2bfloat16_rn(v - __bfloat162float(h));
        size_t o = (size_t)z * D * D + (size_t)(n0 + ty + i * 8) * D + (k0 + tx);
        hi[o] = h;
        lo[o] = l;
    }
}

// ---------------------------------------------------------------------------
// HMMA bf16x3-split GEMM.  CTA 64x64, BK=32, 4-stage cp.async, single
// sync/iter, 8 warps 32x16, 3 CTAs/SM (register-capped).
// EPI: 0 none / 1 relu / 2 gelu.  OUT: 0 fp32 C / 1 split (Ch, Cl).
// Stage: Ah 4K | Al 4K | Bh 4K | Bl 4K = 16K.
// ---------------------------------------------------------------------------
#define STG_BYTES 16384
#define NSTAGE 4
#define NITER  24
#define GEMM_SMEM (NSTAGE * STG_BYTES + 1024)

template <int EPI, int OUT>
__global__ __launch_bounds__(256, 3) void gemm_mma(
    const bf16* __restrict__ Ah, const bf16* __restrict__ Al,
    const bf16* __restrict__ Bh, const bf16* __restrict__ Bl,
    const float* __restrict__ bias, float* __restrict__ C,
    bf16* __restrict__ Ch, bf16* __restrict__ Cl, int M)
{
    extern __shared__ char dsm[];
    uint32_t raw  = smem_u32(dsm);
    uint32_t base = (raw + 1023u) & ~1023u;

    const int tid  = threadIdx.x;
    const int lane = tid & 31, wid = tid >> 5;
    const int bm = blockIdx.y * 64, bn = blockIdx.x * 64;
    const int warp_m = (wid & 1) * 32, warp_n = (wid >> 1) * 16;

    float acc[2][2][4];
    #pragma unroll
    for (int i = 0; i < 2; i++)
        #pragma unroll
        for (int j = 0; j < 2; j++)
            #pragma unroll
            for (int q = 0; q < 4; q++) acc[i][j][q] = 0.f;

    auto prefetch = [&](int c) {
        uint32_t sb = base + (uint32_t)(c & (NSTAGE - 1)) * STG_BYTES;
        int k0 = c * 32;
        #pragma unroll
        for (int r = 0; r < 4; r++) {
            int u = tid + r * 256;                 // 0..1023 (16B chunks)
            const bf16* gp;
            uint32_t so;
            int nb = 16;
            int mat, idx;
            if (u < 512) {                          // A: Ah(256) Al(256)
                mat = u >> 8; idx = u & 255;
                int row = idx >> 2, c16 = idx & 3;
                so = sb + (uint32_t)mat * 4096u + sw64((uint32_t)(row * 64 + c16 * 16));
                int grow = bm + row;
                int cl = (grow < M) ? grow : 0;
                if (grow >= M) nb = 0;
                gp = (mat == 0 ? Ah : Al) + (size_t)cl * D + k0 + c16 * 8;
            } else {                                // B: Bh(256) Bl(256)
                int v = u - 512;
                mat = v >> 8; idx = v & 255;
                int row = idx >> 2, c16 = idx & 3;
                so = sb + 8192u + (uint32_t)mat * 4096u
                   + sw64((uint32_t)(row * 64 + c16 * 16));
                gp = (mat == 0 ? Bh : Bl) + (size_t)(bn + row) * D + k0 + c16 * 8;
            }
            asm volatile("cp.async.cg.shared.global [%0], [%1], 16, %2;"
                         :: "r"(so), "l"(gp), "r"(nb));
        }
        asm volatile("cp.async.commit_group;" ::: "memory");
    };

    prefetch(0);
    prefetch(1);
    prefetch(2);

    const uint32_t aRB = (uint32_t)((warp_m + (lane & 15)) * 64 + (lane >> 4) * 16);
    const uint32_t bRB = (uint32_t)((warp_n + (lane & 7) + ((lane >> 4) << 3)) * 64
                                    + ((lane >> 3) & 1) * 16);

    for (int c = 0; c < NITER; c++) {
        if      (c < NITER - 2)  asm volatile("cp.async.wait_group 2;" ::: "memory");
        else if (c == NITER - 2) asm volatile("cp.async.wait_group 1;" ::: "memory");
        else                     asm volatile("cp.async.wait_group 0;" ::: "memory");
        __syncthreads();
        if (c + 3 < NITER) prefetch(c + 3);   // writes stage (c-1)%4: consumed pre-sync

        uint32_t sb = base + (uint32_t)(c & (NSTAGE - 1)) * STG_BYTES;
        #pragma unroll
        for (int ks = 0; ks < 2; ks++) {
            uint32_t ah[2][4], al[2][4], bh[2][2], bl[2][2];
            #pragma unroll
            for (int mf = 0; mf < 2; mf++) {
                uint32_t off = aRB + mf * 1024 + ks * 32;
                ldm_x4(ah[mf], sb + sw64(off));
                ldm_x4(al[mf], sb + 4096u + sw64(off));
            }
            {
                uint32_t off = bRB + ks * 32;
                uint32_t t[4];
                ldm_x4(t, sb + 8192u + sw64(off));
                bh[0][0] = t[0]; bh[0][1] = t[1];
                bh[1][0] = t[2]; bh[1][1] = t[3];
                ldm_x4(t, sb + 12288u + sw64(off));
                bl[0][0] = t[0]; bl[0][1] = t[1];
                bl[1][0] = t[2]; bl[1][1] = t[3];
            }
            #pragma unroll
            for (int mf = 0; mf < 2; mf++)
                #pragma unroll
                for (int nf = 0; nf < 2; nf++) {
                    mma_bf16(acc[mf][nf], ah[mf], bh[nf]);
                    mma_bf16(acc[mf][nf], ah[mf], bl[nf]);
                    mma_bf16(acc[mf][nf], al[mf], bh[nf]);
                }
        }
    }

    // ---- epilogue -----------------------------------------------------------
    const int grp = lane >> 2, tig = lane & 3;
    #pragma unroll
    for (int mf = 0; mf < 2; mf++) {
        #pragma unroll
        for (int h2 = 0; h2 < 2; h2++) {
            int row = bm + warp_m + mf * 16 + grp + h2 * 8;
            if (row >= M) continue;
            #pragma unroll
            for (int nf = 0; nf < 2; nf++) {
                int col = bn + warp_n + nf * 8 + tig * 2;
                float v0 = acc[mf][nf][h2 * 2 + 0] + __ldg(&bias[col]);
                float v1 = acc[mf][nf][h2 * 2 + 1] + __ldg(&bias[col + 1]);
                if (EPI == 1) { v0 = fmaxf(v0, 0.f); v1 = fmaxf(v1, 0.f); }
                else if (EPI == 2) { v0 = gelu_f(v0); v1 = gelu_f(v1); }
                if (OUT == 1) {
                    bf16 h0 = __float2bfloat16_rn(v0), h1 = __float2bfloat16_rn(v1);
                    bf16 l0 = __float2bfloat16_rn(v0 - __bfloat162float(h0));
                    bf16 l1 = __float2bfloat16_rn(v1 - __bfloat162float(h1));
                    *(__nv_bfloat162*)(Ch + (size_t)row * D + col) = __halves2bfloat162(h0, h1);
                    *(__nv_bfloat162*)(Cl + (size_t)row * D + col) = __halves2bfloat162(l0, l1);
                } else {
                    *(float2*)(C + (size_t)row * D + col) = make_float2(v0, v1);
                }
            }
        }
    }
}

// ---------------------------------------------------------------------------
// Fused embedding-sum + LayerNorm -> pre-split bf16 hi/lo.  192 thr, float4.
// ids == nullptr -> synthesize ids from row index (bond table 8x8x8).
// ---------------------------------------------------------------------------
__global__ void encode_embed_ln(const int* __restrict__ ids, int F, int V,
                                const float* __restrict__ emb,
                                const float* __restrict__ g,
                                const float* __restrict__ b,
                                bf16* __restrict__ oh, bf16* __restrict__ ol, int M)
{
    int row = blockIdx.x;
    if (row >= M) return;
    __shared__ int   sid[16];
    __shared__ float sred[2][6];
    __shared__ float smv[2];
    int tid = threadIdx.x;              // 0..191
    int c = tid * 4;
    if (ids) {
        if (tid < F) sid[tid] = ids[(size_t)row * F + tid];
    } else if (tid == 0) {
        sid[0] = row >> 6; sid[1] = (row >> 3) & 7; sid[2] = row & 7;
    }
    __syncthreads();

    float4 v = make_float4(0.f, 0.f, 0.f, 0.f);
    for (int f = 0; f < F; f++) {
        float4 e = *(const float4*)(emb + ((size_t)f * V + sid[f]) * D + c);
        v.x += e.x; v.y += e.y; v.z += e.z; v.w += e.w;
    }
    float s = v.x + v.y + v.z + v.w;
    float q = v.x * v.x + v.y * v.y + v.z * v.z + v.w * v.w;
    #pragma unroll
    for (int off = 16; off; off >>= 1) {
        s += __shfl_down_sync(0xffffffffu, s, off);
        q += __shfl_down_sync(0xffffffffu, q, off);
    }
    int wid = tid >> 5, lane = tid & 31;
    if (lane == 0) { sred[0][wid] = s; sred[1][wid] = q; }
    __syncthreads();
    if (tid == 0) {
        float ss = 0.f, qq = 0.f;
        #pragma unroll
        for (int i = 0; i < 6; i++) { ss += sred[0][i]; qq += sred[1][i]; }
        float mean = ss * (1.0f / D);
        float var  = qq * (1.0f / D) - mean * mean;
        smv[0] = mean;
        smv[1] = rsqrtf(var + 1e-5f);
    }
    __syncthreads();
    float mean = smv[0], rstd = smv[1];
    float4 gg = *(const float4*)(g + c);
    float4 bb = *(const float4*)(b + c);
    float4 o;
    o.x = (v.x - mean) * rstd * gg.x + bb.x;
    o.y = (v.y - mean) * rstd * gg.y + bb.y;
    o.z = (v.z - mean) * rstd * gg.z + bb.z;
    o.w = (v.w - mean) * rstd * gg.w + bb.w;
    uint2 hp, lp;
    split4(o, hp, lp);
    *(uint2*)(oh + (size_t)row * D + c) = hp;
    *(uint2*)(ol + (size_t)row * D + c) = lp;
}

// ---------------------------------------------------------------------------
// CSR build: histogram, block scan, fill (packed src | etype<<16)
// ---------------------------------------------------------------------------
__global__ void deg_hist(const int* __restrict__ dst, int* __restrict__ deg, int E)
{
    int e = blockIdx.x * blockDim.x + threadIdx.x;
    if (e < E) atomicAdd(&deg[dst[e]], 1);
}

__global__ void deg_scan(const int* __restrict__ deg, int* __restrict__ off, int n)
{
    __shared__ int part[1024];
    int tid = threadIdx.x;
    int chunk = (n + 1023) / 1024;
    int start = tid * chunk;
    int end = start + chunk; if (end > n) end = n;
    int s = 0;
    for (int i = start; i < end; i++) s += deg[i];
    part[tid] = s;
    __syncthreads();
    if (tid == 0) {
        int run = 0;
        for (int i = 0; i < 1024; i++) { int t = part[i]; part[i] = run; run += t; }
    }
    __syncthreads();
    int run = part[tid];
    for (int i = start; i < end; i++) { off[i] = run; run += deg[i]; }
    if (end == n && start < n) off[n] = run;
}

__global__ void csr_fill(const int* __restrict__ src, const int* __restrict__ dst,
                         const int* __restrict__ ea, const int* __restrict__ off,
                         int* __restrict__ cur, int* __restrict__ csr, int E)
{
    int e = blockIdx.x * blockDim.x + threadIdx.x;
    if (e >= E) return;
    int d = dst[e];
    int slot = atomicAdd(&cur[d], 1);
    int et = ea[e * 3] * 64 + ea[e * 3 + 1] * 8 + ea[e * 3 + 2];
    csr[off[d] + slot] = src[e] | (et << 16);
}

// ---------------------------------------------------------------------------
// Pull-mode aggregate + split (192 thr, float4, broadcast edge loop):
//   z[row] = h[row] + sum_e relu(h[src_e] + etab[et_e]);  write bf16 split.
// ---------------------------------------------------------------------------
__global__ void aggregate_split(const float* __restrict__ h,
                                const float* __restrict__ etab,
                                const int* __restrict__ off,
                                const int* __restrict__ csr,
                                bf16* __restrict__ sh, bf16* __restrict__ sl, int Mn)
{
    int row = blockIdx.x;
    if (row >= Mn) return;
    int tid = threadIdx.x;              // 0..191
    int c = tid * 4;
    int o0 = off[row], o1 = off[row + 1];

    float4 acc = *(const float4*)(h + (size_t)row * D + c);
    for (int j = o0; j < o1; j++) {
        int p = __ldg(&csr[j]);         // uniform across block -> broadcast
        int s = p & 0xFFFF;
        int et = p >> 16;
        float4 hv = *(const float4*)(h + (size_t)s * D + c);
        float4 ev = *(const float4*)(etab + (size_t)et * D + c);
        acc.x += fmaxf(hv.x + ev.x, 0.f);
        acc.y += fmaxf(hv.y + ev.y, 0.f);
        acc.z += fmaxf(hv.z + ev.z, 0.f);
        acc.w += fmaxf(hv.w + ev.w, 0.f);
    }
    uint2 hp, lp;
    split4(acc, hp, lp);
    *(uint2*)(sh + (size_t)row * D + c) = hp;
    *(uint2*)(sl + (size_t)row * D + c) = lp;
}

// ---------------------------------------------------------------------------
// Fused gelu + residual + LayerNorm (h in place).  192 thr, float4.
// ---------------------------------------------------------------------------
__global__ void gelu_res_ln(const float* __restrict__ u, float* __restrict__ h,
                            const float* __restrict__ g,
                            const float* __restrict__ b, int M)
{
    int row = blockIdx.x;
    if (row >= M) return;
    __shared__ float sred[2][6];
    __shared__ float smv[2];
    int tid = threadIdx.x;              // 0..191
    int c = tid * 4;

    float4 uu = *(const float4*)(u + (size_t)row * D + c);
    float4 hh = *(const float4*)(h + (size_t)row * D + c);
    float4 v;
    v.x = gelu_f(uu.x) + hh.x;
    v.y = gelu_f(uu.y) + hh.y;
    v.z = gelu_f(uu.z) + hh.z;
    v.w = gelu_f(uu.w) + hh.w;
    float s = v.x + v.y + v.z + v.w;
    float q = v.x * v.x + v.y * v.y + v.z * v.z + v.w * v.w;
    #pragma unroll
    for (int off = 16; off; off >>= 1) {
        s += __shfl_down_sync(0xffffffffu, s, off);
        q += __shfl_down_sync(0xffffffffu, q, off);
    }
    int wid = tid >> 5, lane = tid & 31;
    if (lane == 0) { sred[0][wid] = s; sred[1][wid] = q; }
    __syncthreads();
    if (tid == 0) {
        float ss = 0.f, qq = 0.f;
        #pragma unroll
        for (int i = 0; i < 6; i++) { ss += sred[0][i]; qq += sred[1][i]; }
        float mean = ss * (1.0f / D);
        float var  = qq * (1.0f / D) - mean * mean;
        smv[0] = mean;
        smv[1] = rsqrtf(var + 1e-5f);
    }
    __syncthreads();
    float mean = smv[0], rstd = smv[1];
    float4 gg = *(const float4*)(g + c);
    float4 bb = *(const float4*)(b + c);
    float4 o;
    o.x = (v.x - mean) * rstd * gg.x + bb.x;
    o.y = (v.y - mean) * rstd * gg.y + bb.y;
    o.z = (v.z - mean) * rstd * gg.z + bb.z;
    o.w = (v.w - mean) * rstd * gg.w + bb.w;
    *(float4*)(h + (size_t)row * D + c) = o;
}

// ---------------------------------------------------------------------------
extern "C" void kernel_launch(void* const* d_in, const int* in_sizes, int n_in,
                              void* d_out, int out_size)
{
    const int*   x         = (const int*)d_in[0];
    const int*   edge_attr = (const int*)d_in[1];
    const int*   edge_index= (const int*)d_in[2];
    const float* atom_emb  = (const float*)d_in[3];
    const float* atom_ln_g = (const float*)d_in[4];
    const float* atom_ln_b = (const float*)d_in[5];
    const float* atom_w1   = (const float*)d_in[6];
    const float* atom_b1   = (const float*)d_in[7];
    const float* atom_w2   = (const float*)d_in[8];
    const float* atom_b2   = (const float*)d_in[9];
    const float* bond_emb  = (const float*)d_in[10];
    const float* bond_ln_g = (const float*)d_in[11];
    const float* bond_ln_b = (const float*)d_in[12];
    const float* bond_w1   = (const float*)d_in[13];
    const float* bond_b1   = (const float*)d_in[14];
    const float* bond_w2   = (const float*)d_in[15];
    const float* bond_b2   = (const float*)d_in[16];
    const float* conv_w1   = (const float*)d_in[17];
    const float* conv_b1   = (const float*)d_in[18];
    const float* conv_w2   = (const float*)d_in[19];
    const float* conv_b2   = (const float*)d_in[20];
    const float* ln_g      = (const float*)d_in[21];
    const float* ln_b      = (const float*)d_in[22];

    int N = in_sizes[0] / 9;
    int E = in_sizes[1] / 3;
    const int* src = edge_index;
    const int* dst = edge_index + E;
    float* h = (float*)d_out;

    float *etab, *u;
    int *deg, *off, *cur, *csr;
    bf16 *s0h, *s0l, *s1h, *s1l, *wthi, *wtlo;
    cudaGetSymbolAddress((void**)&etab, g_e);
    cudaGetSymbolAddress((void**)&u,    g_u);
    cudaGetSymbolAddress((void**)&deg,  g_deg);
    cudaGetSymbolAddress((void**)&off,  g_off);
    cudaGetSymbolAddress((void**)&cur,  g_cur);
    cudaGetSymbolAddress((void**)&csr,  g_csr);
    cudaGetSymbolAddress((void**)&s0h,  g_s0h);
    cudaGetSymbolAddress((void**)&s0l,  g_s0l);
    cudaGetSymbolAddress((void**)&s1h,  g_s1h);
    cudaGetSymbolAddress((void**)&s1l,  g_s1l);
    cudaGetSymbolAddress((void**)&wthi, g_wthi);
    cudaGetSymbolAddress((void**)&wtlo, g_wtlo);

    cudaFuncSetAttribute(gemm_mma<2, 1>, cudaFuncAttributeMaxDynamicSharedMemorySize, GEMM_SMEM);
    cudaFuncSetAttribute(gemm_mma<1, 1>, cudaFuncAttributeMaxDynamicSharedMemorySize, GEMM_SMEM);
    cudaFuncSetAttribute(gemm_mma<0, 0>, cudaFuncAttributeMaxDynamicSharedMemorySize, GEMM_SMEM);

    const size_t WSZ = (size_t)D * D;

    // pre-transpose + split all 12 weight matrices
    split_transpose_w<<<dim3(24, 24, 12), dim3(32, 8)>>>(
        atom_w1, atom_w2, bond_w1, bond_w2, conv_w1, conv_w2, wthi, wtlo);

    // CSR build (per replay; ~50us)
    cudaMemsetAsync(deg, 0, N * sizeof(int));
    cudaMemsetAsync(cur, 0, N * sizeof(int));
    deg_hist<<<(E + 255) / 256, 256>>>(dst, deg, E);
    deg_scan<<<1, 1024>>>(deg, off, N);
    csr_fill<<<(E + 255) / 256, 256>>>(src, dst, edge_attr, off, cur, csr, E);

    dim3 gN(12, (N + 63) / 64);
    dim3 gT(12, 8);                     // 512-row bond table

    // --- Bond-type table (512 distinct edge types) -> etab ---
    encode_embed_ln<<<512, 192>>>(nullptr, 3, 8, bond_emb, bond_ln_g, bond_ln_b, s0h, s0l, 512);
    gemm_mma<2, 1><<<gT, 256, GEMM_SMEM>>>(s0h, s0l, wthi + 2 * WSZ, wtlo + 2 * WSZ,
                                           bond_b1, nullptr, s1h, s1l, 512);
    gemm_mma<0, 0><<<gT, 256, GEMM_SMEM>>>(s1h, s1l, wthi + 3 * WSZ, wtlo + 3 * WSZ,
                                           bond_b2, etab, nullptr, nullptr, 512);

    // --- Atom encoder: h = gelu(LN(emb) @ w1 + b1) @ w2 + b2 ---
    encode_embed_ln<<<N, 192>>>(x, 9, 128, atom_emb, atom_ln_g, atom_ln_b, s0h, s0l, N);
    gemm_mma<2, 1><<<gN, 256, GEMM_SMEM>>>(s0h, s0l, wthi + 0 * WSZ, wtlo + 0 * WSZ,
                                           atom_b1, nullptr, s1h, s1l, N);
    gemm_mma<0, 0><<<gN, 256, GEMM_SMEM>>>(s1h, s1l, wthi + 1 * WSZ, wtlo + 1 * WSZ,
                                           atom_b2, h, nullptr, nullptr, N);

    // --- 4 GINE layers: aggregate+split -> GEMM1 -> GEMM2 -> LN ---
    for (int l = 0; l < 4; l++) {
        aggregate_split<<<N, 192>>>(h, etab, off, csr, s0h, s0l, N);
        gemm_mma<1, 1><<<gN, 256, GEMM_SMEM>>>(s0h, s0l, wthi + (4 + l) * WSZ, wtlo + (4 + l) * WSZ,
                                               conv_b1 + (size_t)l * D, nullptr, s1h, s1l, N);
        gemm_mma<0, 0><<<gN, 256, GEMM_SMEM>>>(s1h, s1l, wthi + (8 + l) * WSZ, wtlo + (8 + l) * WSZ,
                                               conv_b2 + (size_t)l * D, u, nullptr, nullptr, N);
        gelu_res_ln<<<N, 192>>>(u, h, ln_g + (size_t)l * D, ln_b + (size_t)l * D, N);
    }
}

// round 13
// speedup vs baseline: 1.0872x; 1.0872x over previous
#include <cuda_runtime.h>
#include <cuda_bf16.h>
#include <math.h>
#include <stdint.h>

#define D 768
#define MAXN 50000
#define MAXE 100000

typedef __nv_bfloat16 bf16;

// ---------------- scratch (__device__ globals; no allocations allowed) ------
__device__ float g_e[(size_t)512 * D];        // bond-type table (512 rows)
__device__ float g_u[(size_t)MAXN * D];       // layer MLP output (fp32)
__device__ int   g_deg[MAXN];                 // degree histogram
__device__ int   g_off[MAXN + 1];             // CSR offsets
__device__ int   g_cur[MAXN];                 // fill cursors
__device__ int   g_csr[MAXE];                 // packed (src | etype<<16) by dst
__device__ bf16  g_s0h[(size_t)MAXN * D];     // GEMM1 input, split hi
__device__ bf16  g_s0l[(size_t)MAXN * D];     //                    lo
__device__ bf16  g_s1h[(size_t)MAXN * D];     // GEMM2 input, split hi
__device__ bf16  g_s1l[(size_t)MAXN * D];     //                    lo
__device__ bf16  g_wthi[(size_t)12 * D * D];  // W^T split hi  [z][n][k]
__device__ bf16  g_wtlo[(size_t)12 * D * D];  // W^T split lo

__device__ __forceinline__ float gelu_f(float x) {
    float x3 = x * x * x;
    return 0.5f * x * (1.0f + tanhf(0.7978845608028654f * (x + 0.044715f * x3)));
}
__device__ __forceinline__ uint32_t smem_u32(const void* p) {
    uint32_t a;
    asm("{ .reg .u64 t; cvta.to.shared.u64 t, %1; cvt.u32.u64 %0, t; }" : "=r"(a) : "l"(p));
    return a;
}
__device__ __forceinline__ uint32_t sw64(uint32_t off) { return off ^ ((off >> 3) & 0x30); }

__device__ __forceinline__ void ldm_x4(uint32_t* r, uint32_t a) {
    asm volatile("ldmatrix.sync.aligned.m8n8.x4.shared.b16 {%0,%1,%2,%3}, [%4];"
        : "=r"(r[0]), "=r"(r[1]), "=r"(r[2]), "=r"(r[3]) : "r"(a));
}
__device__ __forceinline__ void mma_bf16(float* c, const uint32_t* a, const uint32_t* b) {
    asm volatile("mma.sync.aligned.m16n8k16.row.col.f32.bf16.bf16.f32 "
        "{%0,%1,%2,%3},{%4,%5,%6,%7},{%8,%9},{%0,%1,%2,%3};"
        : "+f"(c[0]), "+f"(c[1]), "+f"(c[2]), "+f"(c[3])
        : "r"(a[0]), "r"(a[1]), "r"(a[2]), "r"(a[3]), "r"(b[0]), "r"(b[1]));
}
// pack 4 fp32 -> (hi uint2, lo uint2) bf16 split
__device__ __forceinline__ void split4(float4 a, uint2& hp, uint2& lp) {
    bf16 h0 = __float2bfloat16_rn(a.x), h1 = __float2bfloat16_rn(a.y);
    bf16 h2 = __float2bfloat16_rn(a.z), h3 = __float2bfloat16_rn(a.w);
    bf16 l0 = __float2bfloat16_rn(a.x - __bfloat162float(h0));
    bf16 l1 = __float2bfloat16_rn(a.y - __bfloat162float(h1));
    bf16 l2 = __float2bfloat16_rn(a.z - __bfloat162float(h2));
    bf16 l3 = __float2bfloat16_rn(a.w - __bfloat162float(h3));
    __nv_bfloat162 a0 = __halves2bfloat162(h0, h1), a1 = __halves2bfloat162(h2, h3);
    __nv_bfloat162 b0 = __halves2bfloat162(l0, l1), b1 = __halves2bfloat162(l2, l3);
    hp = make_uint2(*(uint32_t*)&a0, *(uint32_t*)&a1);
    lp = make_uint2(*(uint32_t*)&b0, *(uint32_t*)&b1);
}

// ---------------------------------------------------------------------------
// W transpose + bf16 split:  Wt_hi/lo[z][n][k] = split(W_z[k][n])
// ---------------------------------------------------------------------------
__global__ void split_transpose_w(const float* __restrict__ aw1, const float* __restrict__ aw2,
                                  const float* __restrict__ bw1, const float* __restrict__ bw2,
                                  const float* __restrict__ cw1, const float* __restrict__ cw2,
                                  bf16* __restrict__ hi, bf16* __restrict__ lo)
{
    __shared__ float t[32][33];
    int z = blockIdx.z;
    const float* W;
    if      (z == 0) W = aw1;
    else if (z == 1) W = aw2;
    else if (z == 2) W = bw1;
    else if (z == 3) W = bw2;
    else if (z < 8)  W = cw1 + (size_t)(z - 4) * D * D;
    else             W = cw2 + (size_t)(z - 8) * D * D;

    int n0 = blockIdx.x * 32, k0 = blockIdx.y * 32;
    int tx = threadIdx.x, ty = threadIdx.y;     // (32, 8)
    #pragma unroll
    for (int i = 0; i < 4; i++)
        t[ty + i * 8][tx] = W[(size_t)(k0 + ty + i * 8) * D + n0 + tx];
    __syncthreads();
    #pragma unroll
    for (int i = 0; i < 4; i++) {
        float v = t[tx][ty + i * 8];
        bf16 h = __float2bfloat16_rn(v);
        bf16 l = __float2bfloat16_rn(v - __bfloat162float(h));
        size_t o = (size_t)z * D * D + (size_t)(n0 + ty + i * 8) * D + (k0 + tx);
        hi[o] = h;
        lo[o] = l;
    }
}

// ---------------------------------------------------------------------------
// HMMA bf16x3-split GEMM.  CTA 64x128, BK=32, 3-stage cp.async, single
// sync/iter, 8 warps 32x32, 3 CTAs/SM (register-capped at 85).
// EPI: 0 none / 1 relu / 2 gelu.  OUT: 0 fp32 C / 1 split (Ch, Cl).
// Stage: Ah 4K | Al 4K | Bh 8K | Bl 8K = 24K.
// ---------------------------------------------------------------------------
#define STG_BYTES 24576
#define NSTAGE 3
#define NITER  24
#define GEMM_SMEM (NSTAGE * STG_BYTES + 1024)

template <int EPI, int OUT>
__global__ __launch_bounds__(256, 3) void gemm_mma(
    const bf16* __restrict__ Ah, const bf16* __restrict__ Al,
    const bf16* __restrict__ Bh, const bf16* __restrict__ Bl,
    const float* __restrict__ bias, float* __restrict__ C,
    bf16* __restrict__ Ch, bf16* __restrict__ Cl, int M)
{
    extern __shared__ char dsm[];
    uint32_t raw  = smem_u32(dsm);
    uint32_t base = (raw + 1023u) & ~1023u;

    const int tid  = threadIdx.x;
    const int lane = tid & 31, wid = tid >> 5;
    const int bm = blockIdx.y * 64, bn = blockIdx.x * 128;
    const int warp_m = (wid & 1) * 32, warp_n = (wid >> 1) * 32;

    float acc[2][4][4];
    #pragma unroll
    for (int i = 0; i < 2; i++)
        #pragma unroll
        for (int j = 0; j < 4; j++)
            #pragma unroll
            for (int q = 0; q < 4; q++) acc[i][j][q] = 0.f;

    auto prefetch = [&](int c) {
        uint32_t sb = base + (uint32_t)(c % NSTAGE) * STG_BYTES;
        int k0 = c * 32;
        #pragma unroll
        for (int r = 0; r < 6; r++) {
            int u = tid + r * 256;                 // 0..1535 (16B chunks)
            const bf16* gp;
            uint32_t so;
            int nb = 16;
            if (u < 512) {                          // A: Ah(256) Al(256)
                int mat = u >> 8, idx = u & 255;
                int row = idx >> 2, c16 = idx & 3;
                so = sb + (uint32_t)mat * 4096u + sw64((uint32_t)(row * 64 + c16 * 16));
                int grow = bm + row;
                int cl = (grow < M) ? grow : 0;
                if (grow >= M) nb = 0;
                gp = (mat == 0 ? Ah : Al) + (size_t)cl * D + k0 + c16 * 8;
            } else {                                // B: Bh(512) Bl(512)
                int v = u - 512;
                int mat = v >> 9, idx = v & 511;
                int row = idx >> 2, c16 = idx & 3;
                so = sb + 8192u + (uint32_t)mat * 8192u
                   + sw64((uint32_t)(row * 64 + c16 * 16));
                gp = (mat == 0 ? Bh : Bl) + (size_t)(bn + row) * D + k0 + c16 * 8;
            }
            asm volatile("cp.async.cg.shared.global [%0], [%1], 16, %2;"
                         :: "r"(so), "l"(gp), "r"(nb));
        }
        asm volatile("cp.async.commit_group;" ::: "memory");
    };

    prefetch(0);
    prefetch(1);

    const uint32_t aRB = (uint32_t)((warp_m + (lane & 15)) * 64 + (lane >> 4) * 16);
    const uint32_t bRB = (uint32_t)((warp_n + (lane & 7) + ((lane >> 4) << 3)) * 64
                                    + ((lane >> 3) & 1) * 16);

    for (int c = 0; c < NITER; c++) {
        if (c < NITER - 1) asm volatile("cp.async.wait_group 1;" ::: "memory");
        else               asm volatile("cp.async.wait_group 0;" ::: "memory");
        __syncthreads();
        if (c + 2 < NITER) prefetch(c + 2);   // writes stage (c-1)%3: consumed pre-sync

        uint32_t sb = base + (uint32_t)(c % NSTAGE) * STG_BYTES;
        #pragma unroll
        for (int ks = 0; ks < 2; ks++) {
            uint32_t ah[2][4], al[2][4], bh[4][2], bl[4][2];
            #pragma unroll
            for (int mf = 0; mf < 2; mf++) {
                uint32_t off = aRB + mf * 1024 + ks * 32;
                ldm_x4(ah[mf], sb + sw64(off));
                ldm_x4(al[mf], sb + 4096u + sw64(off));
            }
            #pragma unroll
            for (int n2 = 0; n2 < 2; n2++) {
                uint32_t off = bRB + n2 * 1024 + ks * 32;
                uint32_t t[4];
                ldm_x4(t, sb + 8192u + sw64(off));
                bh[n2 * 2][0] = t[0]; bh[n2 * 2][1] = t[1];
                bh[n2 * 2 + 1][0] = t[2]; bh[n2 * 2 + 1][1] = t[3];
                ldm_x4(t, sb + 16384u + sw64(off));
                bl[n2 * 2][0] = t[0]; bl[n2 * 2][1] = t[1];
                bl[n2 * 2 + 1][0] = t[2]; bl[n2 * 2 + 1][1] = t[3];
            }
            #pragma unroll
            for (int mf = 0; mf < 2; mf++)
                #pragma unroll
                for (int nf = 0; nf < 4; nf++) {
                    mma_bf16(acc[mf][nf], ah[mf], bh[nf]);
                    mma_bf16(acc[mf][nf], ah[mf], bl[nf]);
                    mma_bf16(acc[mf][nf], al[mf], bh[nf]);
                }
        }
    }

    // ---- epilogue -----------------------------------------------------------
    const int grp = lane >> 2, tig = lane & 3;
    #pragma unroll
    for (int mf = 0; mf < 2; mf++) {
        #pragma unroll
        for (int h2 = 0; h2 < 2; h2++) {
            int row = bm + warp_m + mf * 16 + grp + h2 * 8;
            if (row >= M) continue;
            #pragma unroll
            for (int nf = 0; nf < 4; nf++) {
                int col = bn + warp_n + nf * 8 + tig * 2;
                float v0 = acc[mf][nf][h2 * 2 + 0] + __ldg(&bias[col]);
                float v1 = acc[mf][nf][h2 * 2 + 1] + __ldg(&bias[col + 1]);
                if (EPI == 1) { v0 = fmaxf(v0, 0.f); v1 = fmaxf(v1, 0.f); }
                else if (EPI == 2) { v0 = gelu_f(v0); v1 = gelu_f(v1); }
                if (OUT == 1) {
                    bf16 h0 = __float2bfloat16_rn(v0), h1 = __float2bfloat16_rn(v1);
                    bf16 l0 = __float2bfloat16_rn(v0 - __bfloat162float(h0));
                    bf16 l1 = __float2bfloat16_rn(v1 - __bfloat162float(h1));
                    *(__nv_bfloat162*)(Ch + (size_t)row * D + col) = __halves2bfloat162(h0, h1);
                    *(__nv_bfloat162*)(Cl + (size_t)row * D + col) = __halves2bfloat162(l0, l1);
                } else {
                    *(float2*)(C + (size_t)row * D + col) = make_float2(v0, v1);
                }
            }
        }
    }
}

// ---------------------------------------------------------------------------
// Fused embedding-sum + LayerNorm -> pre-split bf16 hi/lo.  192 thr, float4.
// ids == nullptr -> synthesize ids from row index (bond table 8x8x8).
// ---------------------------------------------------------------------------
__global__ void encode_embed_ln(const int* __restrict__ ids, int F, int V,
                                const float* __restrict__ emb,
                                const float* __restrict__ g,
                                const float* __restrict__ b,
                                bf16* __restrict__ oh, bf16* __restrict__ ol, int M)
{
    int row = blockIdx.x;
    if (row >= M) return;
    __shared__ int   sid[16];
    __shared__ float sred[2][6];
    __shared__ float smv[2];
    int tid = threadIdx.x;              // 0..191
    int c = tid * 4;
    if (ids) {
        if (tid < F) sid[tid] = ids[(size_t)row * F + tid];
    } else if (tid == 0) {
        sid[0] = row >> 6; sid[1] = (row >> 3) & 7; sid[2] = row & 7;
    }
    __syncthreads();

    float4 v = make_float4(0.f, 0.f, 0.f, 0.f);
    for (int f = 0; f < F; f++) {
        float4 e = *(const float4*)(emb + ((size_t)f * V + sid[f]) * D + c);
        v.x += e.x; v.y += e.y; v.z += e.z; v.w += e.w;
    }
    float s = v.x + v.y + v.z + v.w;
    float q = v.x * v.x + v.y * v.y + v.z * v.z + v.w * v.w;
    #pragma unroll
    for (int off = 16; off; off >>= 1) {
        s += __shfl_down_sync(0xffffffffu, s, off);
        q += __shfl_down_sync(0xffffffffu, q, off);
    }
    int wid = tid >> 5, lane = tid & 31;
    if (lane == 0) { sred[0][wid] = s; sred[1][wid] = q; }
    __syncthreads();
    if (tid == 0) {
        float ss = 0.f, qq = 0.f;
        #pragma unroll
        for (int i = 0; i < 6; i++) { ss += sred[0][i]; qq += sred[1][i]; }
        float mean = ss * (1.0f / D);
        float var  = qq * (1.0f / D) - mean * mean;
        smv[0] = mean;
        smv[1] = rsqrtf(var + 1e-5f);
    }
    __syncthreads();
    float mean = smv[0], rstd = smv[1];
    float4 gg = *(const float4*)(g + c);
    float4 bb = *(const float4*)(b + c);
    float4 o;
    o.x = (v.x - mean) * rstd * gg.x + bb.x;
    o.y = (v.y - mean) * rstd * gg.y + bb.y;
    o.z = (v.z - mean) * rstd * gg.z + bb.z;
    o.w = (v.w - mean) * rstd * gg.w + bb.w;
    uint2 hp, lp;
    split4(o, hp, lp);
    *(uint2*)(oh + (size_t)row * D + c) = hp;
    *(uint2*)(ol + (size_t)row * D + c) = lp;
}

// ---------------------------------------------------------------------------
// CSR build: histogram, block scan, fill (packed src | etype<<16)
// ---------------------------------------------------------------------------
__global__ void deg_hist(const int* __restrict__ dst, int* __restrict__ deg, int E)
{
    int e = blockIdx.x * blockDim.x + threadIdx.x;
    if (e < E) atomicAdd(&deg[dst[e]], 1);
}

__global__ void deg_scan(const int* __restrict__ deg, int* __restrict__ off, int n)
{
    __shared__ int part[1024];
    int tid = threadIdx.x;
    int chunk = (n + 1023) / 1024;
    int start = tid * chunk;
    int end = start + chunk; if (end > n) end = n;
    int s = 0;
    for (int i = start; i < end; i++) s += deg[i];
    part[tid] = s;
    __syncthreads();
    if (tid == 0) {
        int run = 0;
        for (int i = 0; i < 1024; i++) { int t = part[i]; part[i] = run; run += t; }
    }
    __syncthreads();
    int run = part[tid];
    for (int i = start; i < end; i++) { off[i] = run; run += deg[i]; }
    if (end == n && start < n) off[n] = run;
}

__global__ void csr_fill(const int* __restrict__ src, const int* __restrict__ dst,
                         const int* __restrict__ ea, const int* __restrict__ off,
                         int* __restrict__ cur, int* __restrict__ csr, int E)
{
    int e = blockIdx.x * blockDim.x + threadIdx.x;
    if (e >= E) return;
    int d = dst[e];
    int slot = atomicAdd(&cur[d], 1);
    int et = ea[e * 3] * 64 + ea[e * 3 + 1] * 8 + ea[e * 3 + 2];
    csr[off[d] + slot] = src[e] | (et << 16);
}

// ---------------------------------------------------------------------------
// Pull-mode aggregate + split (192 thr, float4, broadcast edge loop):
//   z[row] = h[row] + sum_e relu(h[src_e] + etab[et_e]);  write bf16 split.
// ---------------------------------------------------------------------------
__global__ void aggregate_split(const float* __restrict__ h,
                                const float* __restrict__ etab,
                                const int* __restrict__ off,
                                const int* __restrict__ csr,
                                bf16* __restrict__ sh, bf16* __restrict__ sl, int Mn)
{
    int row = blockIdx.x;
    if (row >= Mn) return;
    int tid = threadIdx.x;              // 0..191
    int c = tid * 4;
    int o0 = off[row], o1 = off[row + 1];

    float4 acc = *(const float4*)(h + (size_t)row * D + c);
    for (int j = o0; j < o1; j++) {
        int p = __ldg(&csr[j]);         // uniform across block -> broadcast
        int s = p & 0xFFFF;
        int et = p >> 16;
        float4 hv = *(const float4*)(h + (size_t)s * D + c);
        float4 ev = *(const float4*)(etab + (size_t)et * D + c);
        acc.x += fmaxf(hv.x + ev.x, 0.f);
        acc.y += fmaxf(hv.y + ev.y, 0.f);
        acc.z += fmaxf(hv.z + ev.z, 0.f);
        acc.w += fmaxf(hv.w + ev.w, 0.f);
    }
    uint2 hp, lp;
    split4(acc, hp, lp);
    *(uint2*)(sh + (size_t)row * D + c) = hp;
    *(uint2*)(sl + (size_t)row * D + c) = lp;
}

// ---------------------------------------------------------------------------
// Fused gelu + residual + LayerNorm (h in place).  192 thr, float4.
// ---------------------------------------------------------------------------
__global__ void gelu_res_ln(const float* __restrict__ u, float* __restrict__ h,
                            const float* __restrict__ g,
                            const float* __restrict__ b, int M)
{
    int row = blockIdx.x;
    if (row >= M) return;
    __shared__ float sred[2][6];
    __shared__ float smv[2];
    int tid = threadIdx.x;              // 0..191
    int c = tid * 4;

    float4 uu = *(const float4*)(u + (size_t)row * D + c);
    float4 hh = *(const float4*)(h + (size_t)row * D + c);
    float4 v;
    v.x = gelu_f(uu.x) + hh.x;
    v.y = gelu_f(uu.y) + hh.y;
    v.z = gelu_f(uu.z) + hh.z;
    v.w = gelu_f(uu.w) + hh.w;
    float s = v.x + v.y + v.z + v.w;
    float q = v.x * v.x + v.y * v.y + v.z * v.z + v.w * v.w;
    #pragma unroll
    for (int off = 16; off; off >>= 1) {
        s += __shfl_down_sync(0xffffffffu, s, off);
        q += __shfl_down_sync(0xffffffffu, q, off);
    }
    int wid = tid >> 5, lane = tid & 31;
    if (lane == 0) { sred[0][wid] = s; sred[1][wid] = q; }
    __syncthreads();
    if (tid == 0) {
        float ss = 0.f, qq = 0.f;
        #pragma unroll
        for (int i = 0; i < 6; i++) { ss += sred[0][i]; qq += sred[1][i]; }
        float mean = ss * (1.0f / D);
        float var  = qq * (1.0f / D) - mean * mean;
        smv[0] = mean;
        smv[1] = rsqrtf(var + 1e-5f);
    }
    __syncthreads();
    float mean = smv[0], rstd = smv[1];
    float4 gg = *(const float4*)(g + c);
    float4 bb = *(const float4*)(b + c);
    float4 o;
    o.x = (v.x - mean) * rstd * gg.x + bb.x;
    o.y = (v.y - mean) * rstd * gg.y + bb.y;
    o.z = (v.z - mean) * rstd * gg.z + bb.z;
    o.w = (v.w - mean) * rstd * gg.w + bb.w;
    *(float4*)(h + (size_t)row * D + c) = o;
}

// ---------------------------------------------------------------------------
extern "C" void kernel_launch(void* const* d_in, const int* in_sizes, int n_in,
                              void* d_out, int out_size)
{
    const int*   x         = (const int*)d_in[0];
    const int*   edge_attr = (const int*)d_in[1];
    const int*   edge_index= (const int*)d_in[2];
    const float* atom_emb  = (const float*)d_in[3];
    const float* atom_ln_g = (const float*)d_in[4];
    const float* atom_ln_b = (const float*)d_in[5];
    const float* atom_w1   = (const float*)d_in[6];
    const float* atom_b1   = (const float*)d_in[7];
    const float* atom_w2   = (const float*)d_in[8];
    const float* atom_b2   = (const float*)d_in[9];
    const float* bond_emb  = (const float*)d_in[10];
    const float* bond_ln_g = (const float*)d_in[11];
    const float* bond_ln_b = (const float*)d_in[12];
    const float* bond_w1   = (const float*)d_in[13];
    const float* bond_b1   = (const float*)d_in[14];
    const float* bond_w2   = (const float*)d_in[15];
    const float* bond_b2   = (const float*)d_in[16];
    const float* conv_w1   = (const float*)d_in[17];
    const float* conv_b1   = (const float*)d_in[18];
    const float* conv_w2   = (const float*)d_in[19];
    const float* conv_b2   = (const float*)d_in[20];
    const float* ln_g      = (const float*)d_in[21];
    const float* ln_b      = (const float*)d_in[22];

    int N = in_sizes[0] / 9;
    int E = in_sizes[1] / 3;
    const int* src = edge_index;
    const int* dst = edge_index + E;
    float* h = (float*)d_out;

    float *etab, *u;
    int *deg, *off, *cur, *csr;
    bf16 *s0h, *s0l, *s1h, *s1l, *wthi, *wtlo;
    cudaGetSymbolAddress((void**)&etab, g_e);
    cudaGetSymbolAddress((void**)&u,    g_u);
    cudaGetSymbolAddress((void**)&deg,  g_deg);
    cudaGetSymbolAddress((void**)&off,  g_off);
    cudaGetSymbolAddress((void**)&cur,  g_cur);
    cudaGetSymbolAddress((void**)&csr,  g_csr);
    cudaGetSymbolAddress((void**)&s0h,  g_s0h);
    cudaGetSymbolAddress((void**)&s0l,  g_s0l);
    cudaGetSymbolAddress((void**)&s1h,  g_s1h);
    cudaGetSymbolAddress((void**)&s1l,  g_s1l);
    cudaGetSymbolAddress((void**)&wthi, g_wthi);
    cudaGetSymbolAddress((void**)&wtlo, g_wtlo);

    cudaFuncSetAttribute(gemm_mma<2, 1>, cudaFuncAttributeMaxDynamicSharedMemorySize, GEMM_SMEM);
    cudaFuncSetAttribute(gemm_mma<1, 1>, cudaFuncAttributeMaxDynamicSharedMemorySize, GEMM_SMEM);
    cudaFuncSetAttribute(gemm_mma<0, 0>, cudaFuncAttributeMaxDynamicSharedMemorySize, GEMM_SMEM);

    const size_t WSZ = (size_t)D * D;

    // pre-transpose + split all 12 weight matrices
    split_transpose_w<<<dim3(24, 24, 12), dim3(32, 8)>>>(
        atom_w1, atom_w2, bond_w1, bond_w2, conv_w1, conv_w2, wthi, wtlo);

    // CSR build (per replay; ~50us)
    cudaMemsetAsync(deg, 0, N * sizeof(int));
    cudaMemsetAsync(cur, 0, N * sizeof(int));
    deg_hist<<<(E + 255) / 256, 256>>>(dst, deg, E);
    deg_scan<<<1, 1024>>>(deg, off, N);
    csr_fill<<<(E + 255) / 256, 256>>>(src, dst, edge_attr, off, cur, csr, E);

    dim3 gN(6, (N + 63) / 64);
    dim3 gT(6, 8);                      // 512-row bond table

    // --- Bond-type table (512 distinct edge types) -> etab ---
    encode_embed_ln<<<512, 192>>>(nullptr, 3, 8, bond_emb, bond_ln_g, bond_ln_b, s0h, s0l, 512);
    gemm_mma<2, 1><<<gT, 256, GEMM_SMEM>>>(s0h, s0l, wthi + 2 * WSZ, wtlo + 2 * WSZ,
                                           bond_b1, nullptr, s1h, s1l, 512);
    gemm_mma<0, 0><<<gT, 256, GEMM_SMEM>>>(s1h, s1l, wthi + 3 * WSZ, wtlo + 3 * WSZ,
                                           bond_b2, etab, nullptr, nullptr, 512);

    // --- Atom encoder: h = gelu(LN(emb) @ w1 + b1) @ w2 + b2 ---
    encode_embed_ln<<<N, 192>>>(x, 9, 128, atom_emb, atom_ln_g, atom_ln_b, s0h, s0l, N);
    gemm_mma<2, 1><<<gN, 256, GEMM_SMEM>>>(s0h, s0l, wthi + 0 * WSZ, wtlo + 0 * WSZ,
                                           atom_b1, nullptr, s1h, s1l, N);
    gemm_mma<0, 0><<<gN, 256, GEMM_SMEM>>>(s1h, s1l, wthi + 1 * WSZ, wtlo + 1 * WSZ,
                                           atom_b2, h, nullptr, nullptr, N);

    // --- 4 GINE layers: aggregate+split -> GEMM1 -> GEMM2 -> LN ---
    for (int l = 0; l < 4; l++) {
        aggregate_split<<<N, 192>>>(h, etab, off, csr, s0h, s0l, N);
        gemm_mma<1, 1><<<gN, 256, GEMM_SMEM>>>(s0h, s0l, wthi + (4 + l) * WSZ, wtlo + (4 + l) * WSZ,
                                               conv_b1 + (size_t)l * D, nullptr, s1h, s1l, N);
        gemm_mma<0, 0><<<gN, 256, GEMM_SMEM>>>(s1h, s1l, wthi + (8 + l) * WSZ, wtlo + (8 + l) * WSZ,
                                               conv_b2 + (size_t)l * D, u, nullptr, nullptr, N);
        gelu_res_ln<<<N, 192>>>(u, h, ln_g + (size_t)l * D, ln_b + (size_t)l * D, N);
    }
}